// round 4
// baseline (speedup 1.0000x reference)
#include <cuda_runtime.h>
#include <cstdint>

#define D 128
#define N_MAX 50064
#define E_MAX 500000
#define CB 256          // count blocks appended to kernel A

// ---- device scratch (no allocations; .bss is zero at load, kernels keep it clean) ----
__device__ float g_h[(size_t)N_MAX * D];   // h = x @ W  (unscaled)
__device__ int   g_cnt[N_MAX];             // in-degree (excl. self loop); zeroed by k_final
__device__ float g_dis[N_MAX];             // rsqrt(1 + cnt)
__device__ int   g_start[N_MAX];           // CSC segment start (arbitrary disjoint order)
__device__ int   g_cursor[N_MAX];
__device__ int   g_adj[E_MAX];
__device__ int   g_total;                  // ticket counter; zeroed by k_final
__device__ float g_colstats[2 * D];        // zeroed by kernel A each call

// ---------------------------------------------------------------------------
// Kernel A (block-specialized):
//   blocks [0, GB)       : h = x @ W   (fp32x2 packed-FMA GEMM, 128x128 tile)
//   blocks [GB, GB+CB)   : in-degree count over pos edges; block GB zeros colstats
// ---------------------------------------------------------------------------
#define FMA2(acc, a, b) asm("fma.rn.f32x2 %0, %1, %2, %0;" : "+l"(acc) : "l"(a), "l"(b))

__global__ void __launch_bounds__(256) kA(const float* __restrict__ x,
                                          const float* __restrict__ W,
                                          const int* __restrict__ pos,
                                          int N, int E, int GB) {
    if (blockIdx.x >= GB) {
        // ---- count path ----
        int b = blockIdx.x - GB;
        if (b == 0) g_colstats[threadIdx.x] = 0.0f;   // 256 threads == 2*D
        for (int e = b * 256 + threadIdx.x; e < E; e += CB * 256)
            atomicAdd(&g_cnt[pos[(size_t)E + e]], 1);
        return;
    }

    // ---- GEMM path ----
    __shared__ float xs[16][128];   // transposed x tile: xs[k][row]
    __shared__ float ws[16][128];   // W tile: ws[k][col]

    const int t  = threadIdx.x;
    const int r0 = blockIdx.x * 128;
    const int cg = t & 15;          // cols cg*8 .. cg*8+7
    const int rg = t >> 4;          // rows rg*8 .. rg*8+7

    unsigned long long acc[8][4];
#pragma unroll
    for (int i = 0; i < 8; i++)
#pragma unroll
        for (int j = 0; j < 4; j++) acc[i][j] = 0ull;

    for (int k0 = 0; k0 < D; k0 += 16) {
        __syncthreads();
#pragma unroll
        for (int u = 0; u < 2; u++) {
            int id  = t + u * 256;       // 0..511
            int row = id >> 2;           // 0..127
            int kq  = (id & 3) * 4;      // 0,4,8,12
            float4 v = make_float4(0.f, 0.f, 0.f, 0.f);
            int gr = r0 + row;
            if (gr < N) v = *(const float4*)(x + (size_t)gr * D + k0 + kq);
            xs[kq + 0][row] = v.x;
            xs[kq + 1][row] = v.y;
            xs[kq + 2][row] = v.z;
            xs[kq + 3][row] = v.w;
        }
#pragma unroll
        for (int u = 0; u < 2; u++) {
            int id = t + u * 256;
            int kk = id >> 5;
            int c4 = id & 31;
            *(float4*)&ws[kk][c4 * 4] =
                *(const float4*)(W + (size_t)(k0 + kk) * D + c4 * 4);
        }
        __syncthreads();

#pragma unroll
        for (int kk = 0; kk < 16; kk++) {
            ulonglong2 wA = *(const ulonglong2*)&ws[kk][cg * 8];
            ulonglong2 wB = *(const ulonglong2*)&ws[kk][cg * 8 + 4];
            float4 xa = *(const float4*)&xs[kk][rg * 8];
            float4 xb = *(const float4*)&xs[kk][rg * 8 + 4];
            float xv[8] = {xa.x, xa.y, xa.z, xa.w, xb.x, xb.y, xb.z, xb.w};
#pragma unroll
            for (int i = 0; i < 8; i++) {
                unsigned long long xd;
                asm("mov.b64 %0, {%1, %1};" : "=l"(xd) : "f"(xv[i]));
                FMA2(acc[i][0], xd, wA.x);
                FMA2(acc[i][1], xd, wA.y);
                FMA2(acc[i][2], xd, wB.x);
                FMA2(acc[i][3], xd, wB.y);
            }
        }
    }

#pragma unroll
    for (int i = 0; i < 8; i++) {
        int gr = r0 + rg * 8 + i;
        if (gr < N) {
            float2 p0 = *(float2*)&acc[i][0];
            float2 p1 = *(float2*)&acc[i][1];
            float2 p2 = *(float2*)&acc[i][2];
            float2 p3 = *(float2*)&acc[i][3];
            *(float4*)(g_h + (size_t)gr * D + cg * 8)     = make_float4(p0.x, p0.y, p1.x, p1.y);
            *(float4*)(g_h + (size_t)gr * D + cg * 8 + 4) = make_float4(p2.x, p2.y, p3.x, p3.y);
        }
    }
}

// ---------------------------------------------------------------------------
// B: segment allocation — block-local scan + one atomic ticket per block.
//    Segment ORDER is arbitrary; only disjointness matters. Also dis, cursor.
// ---------------------------------------------------------------------------
__global__ void k_alloc(int N) {
    __shared__ int sh[256];
    __shared__ int base;
    int t = threadIdx.x;
    int i = blockIdx.x * 256 + t;
    int c = (i < N) ? g_cnt[i] : 0;
    sh[t] = c;
    __syncthreads();
    for (int off = 1; off < 256; off <<= 1) {   // inclusive scan
        int v = (t >= off) ? sh[t - off] : 0;
        __syncthreads();
        sh[t] += v;
        __syncthreads();
    }
    if (t == 255) base = atomicAdd(&g_total, sh[255]);
    __syncthreads();
    if (i < N) {
        int start = base + sh[t] - c;   // exclusive within block
        g_start[i]  = start;
        g_cursor[i] = start;
        g_dis[i]    = rsqrtf(1.0f + (float)c);
    }
}

// ---------------------------------------------------------------------------
// C: fill CSC adjacency
// ---------------------------------------------------------------------------
__global__ void k_fill(const int* __restrict__ pos, int E) {
    int e = blockIdx.x * blockDim.x + threadIdx.x;
    if (e < E) {
        int col = pos[(size_t)E + e];
        int p = atomicAdd(&g_cursor[col], 1);
        g_adj[p] = pos[e];
    }
}

// ---------------------------------------------------------------------------
// D: gather (warp per node, persistent) + fused column stats:
//    out[c] = dis[c] * ( dis[c]*h[c] + sum_in dis[r]*h[r] )
// ---------------------------------------------------------------------------
__global__ void __launch_bounds__(256) k_gather(float* __restrict__ out, int N) {
    __shared__ float ssum[8][128];
    __shared__ float ssq[8][128];
    int lane = threadIdx.x & 31;
    int w    = threadIdx.x >> 5;

    float4 cs = make_float4(0.f, 0.f, 0.f, 0.f);   // per-lane column sums
    float4 cq = make_float4(0.f, 0.f, 0.f, 0.f);   // per-lane column sumsq

    for (int node = blockIdx.x * 8 + w; node < N; node += gridDim.x * 8) {
        int start = g_start[node];
        int cnt   = g_cnt[node];
        float sc  = g_dis[node];

        float4 h = *(const float4*)(g_h + (size_t)node * D + lane * 4);
        float4 acc = make_float4(sc * h.x, sc * h.y, sc * h.z, sc * h.w);

        for (int j = 0; j < cnt; j += 32) {
            int m = min(32, cnt - j);
            int idx = (lane < m) ? g_adj[start + j + lane] : 0;
            int k = 0;
            for (; k + 4 <= m; k += 4) {
                int rA = __shfl_sync(0xffffffffu, idx, k + 0);
                int rB = __shfl_sync(0xffffffffu, idx, k + 1);
                int rC = __shfl_sync(0xffffffffu, idx, k + 2);
                int rD = __shfl_sync(0xffffffffu, idx, k + 3);
                float dA = g_dis[rA], dB = g_dis[rB], dC = g_dis[rC], dD = g_dis[rD];
                float4 vA = *(const float4*)(g_h + (size_t)rA * D + lane * 4);
                float4 vB = *(const float4*)(g_h + (size_t)rB * D + lane * 4);
                float4 vC = *(const float4*)(g_h + (size_t)rC * D + lane * 4);
                float4 vD = *(const float4*)(g_h + (size_t)rD * D + lane * 4);
                acc.x = fmaf(dA, vA.x, fmaf(dB, vB.x, fmaf(dC, vC.x, fmaf(dD, vD.x, acc.x))));
                acc.y = fmaf(dA, vA.y, fmaf(dB, vB.y, fmaf(dC, vC.y, fmaf(dD, vD.y, acc.y))));
                acc.z = fmaf(dA, vA.z, fmaf(dB, vB.z, fmaf(dC, vC.z, fmaf(dD, vD.z, acc.z))));
                acc.w = fmaf(dA, vA.w, fmaf(dB, vB.w, fmaf(dC, vC.w, fmaf(dD, vD.w, acc.w))));
            }
            for (; k < m; k++) {
                int r = __shfl_sync(0xffffffffu, idx, k);
                float dr = g_dis[r];
                float4 v = *(const float4*)(g_h + (size_t)r * D + lane * 4);
                acc.x = fmaf(dr, v.x, acc.x);
                acc.y = fmaf(dr, v.y, acc.y);
                acc.z = fmaf(dr, v.z, acc.z);
                acc.w = fmaf(dr, v.w, acc.w);
            }
        }

        float4 o = make_float4(acc.x * sc, acc.y * sc, acc.z * sc, acc.w * sc);
        *(float4*)(out + (size_t)node * D + lane * 4) = o;
        cs.x += o.x; cs.y += o.y; cs.z += o.z; cs.w += o.w;
        cq.x += o.x * o.x; cq.y += o.y * o.y; cq.z += o.z * o.z; cq.w += o.w * o.w;
    }

    *(float4*)&ssum[w][lane * 4] = cs;
    *(float4*)&ssq[w][lane * 4]  = cq;
    __syncthreads();
    int t = threadIdx.x;
    if (t < D) {
        float a = 0.f, b = 0.f;
#pragma unroll
        for (int w2 = 0; w2 < 8; w2++) { a += ssum[w2][t]; b += ssq[w2][t]; }
        atomicAdd(&g_colstats[t], a);
        atomicAdd(&g_colstats[D + t], b);
    }
}

// ---------------------------------------------------------------------------
// E: BN (training mode, biased var) + ReLU in place; cleanup cnt/total for
//    the next (replayed) call.
// ---------------------------------------------------------------------------
__global__ void k_final(const float* __restrict__ gamma,
                        const float* __restrict__ beta,
                        float* __restrict__ out, int N) {
    __shared__ float sscale[D], sshift[D];
    int t = threadIdx.x;
    if (t < D) {
        float invN = 1.0f / (float)N;
        float mean = g_colstats[t] * invN;
        float var  = g_colstats[D + t] * invN - mean * mean;
        float inv  = rsqrtf(var + 1e-5f);
        float sc   = gamma[t] * inv;
        sscale[t]  = sc;
        sshift[t]  = beta[t] - mean * sc;
    }
    __syncthreads();

    int gid = blockIdx.x * blockDim.x + t;
    if (gid < N) g_cnt[gid] = 0;          // self-clean for next call
    if (gid == 0) g_total = 0;

    size_t total4 = (size_t)N * (D / 4);
    size_t stride = (size_t)gridDim.x * blockDim.x;
    for (size_t i = (size_t)blockIdx.x * blockDim.x + t; i < total4; i += stride) {
        int c = (int)(i & 31) * 4;
        float4 v = ((float4*)out)[i];
        v.x = fmaxf(v.x * sscale[c + 0] + sshift[c + 0], 0.0f);
        v.y = fmaxf(v.y * sscale[c + 1] + sshift[c + 1], 0.0f);
        v.z = fmaxf(v.z * sscale[c + 2] + sshift[c + 2], 0.0f);
        v.w = fmaxf(v.w * sscale[c + 3] + sshift[c + 3], 0.0f);
        ((float4*)out)[i] = v;
    }
}

// ---------------------------------------------------------------------------
extern "C" void kernel_launch(void* const* d_in, const int* in_sizes, int n_in,
                              void* d_out, int out_size) {
    const float* x     = (const float*)d_in[0];
    const int*   pos   = (const int*)d_in[1];   // int32 (JAX canonicalizes int64)
    // d_in[2] = neg_edge_index: weight 0 => no-op, skipped
    const float* W     = (const float*)d_in[3];
    // d_in[4] = b: cancels exactly inside BatchNorm, skipped
    const float* gamma = (const float*)d_in[5];
    const float* beta  = (const float*)d_in[6];
    float*       out   = (float*)d_out;

    const int N  = in_sizes[0] / D;
    const int E  = in_sizes[1] / 2;
    const int GB = (N + 127) / 128;

    kA      <<<GB + CB, 256>>>(x, W, pos, N, E, GB);
    k_alloc <<<(N + 255) / 256, 256>>>(N);
    k_fill  <<<(E + 255) / 256, 256>>>(pos, E);
    k_gather<<<592, 256>>>(out, N);
    k_final <<<784, 256>>>(gamma, beta, out, N);
}